// round 12
// baseline (speedup 1.0000x reference)
#include <cuda_runtime.h>
#include <cstdint>

// Problem constants
#define T_STEPS 8192
#define D_INP   512
#define HDIM    768      // H
#define G3      2304     // 3*H
#define RTOT    4608     // 2 dirs * 3H
#define DH2     1536     // 2*H
#define NCTA    128      // persistent CTAs (all roles fused)
#define GCTA    64       // CTAs per direction group
#define NWARP   12       // GRU units per CTA per its direction
#define SEQ_THR 384      // seq threads per CTA (warps 4..15)
#define HLP_THR 128      // helper threads per CTA (warps 0..3)
#define NTHR    512
#define NTILE_M 36       // 4608/128 output-col tiles
#define NTILE_T 128      // 8192/64 timestep blocks
#define TILES_PER (NTILE_M * NTILE_T)   // 4608 tiles per GEMM
#define KB      16       // GEMM k-block

// ---------------- scratch (device globals; no allocation allowed) -------------
__device__ float g_Gi0[(size_t)T_STEPS * RTOT];        // W_ih0 @ x + b_ih0
__device__ float g_Gi1[(size_t)T_STEPS * RTOT];        // W_ih1 @ h0seq + b_ih1
__device__ float g_H0[(size_t)(T_STEPS + 1) * DH2];    // layer0 hidden seq
__device__ float g_H1[(size_t)(T_STEPS + 1) * DH2];    // layer1 hidden seq
__device__ unsigned g_cnt[2][2];                       // [layer][dir] step-arrival counters
__device__ unsigned g_blk[2][NTILE_T];                 // [gemm][trow] finished-tile counters

// ---------------- packed f32x2 + sync helpers ---------------------------------
__device__ __forceinline__ unsigned long long fma2(unsigned long long a,
                                                   unsigned long long b,
                                                   unsigned long long c) {
    unsigned long long d;
    asm("fma.rn.f32x2 %0,%1,%2,%3;" : "=l"(d) : "l"(a), "l"(b), "l"(c));
    return d;
}
__device__ __forceinline__ unsigned long long pack2(float x, float y) {
    unsigned long long r;
    asm("mov.b64 %0,{%1,%2};" : "=l"(r) : "f"(x), "f"(y));
    return r;
}
__device__ __forceinline__ float2 unpack2(unsigned long long v) {
    float2 f;
    asm("mov.b64 {%0,%1},%2;" : "=f"(f.x), "=f"(f.y) : "l"(v));
    return f;
}
__device__ __forceinline__ unsigned ldrelax(const unsigned* p) {
    unsigned v;
    asm volatile("ld.relaxed.gpu.global.u32 %0,[%1];" : "=r"(v) : "l"(p));
    return v;
}
__device__ __forceinline__ void fence_acqrel() {
    asm volatile("fence.acq_rel.gpu;" ::: "memory");
}
__device__ __forceinline__ void red_add(unsigned* p) {
    asm volatile("red.relaxed.gpu.global.add.u32 [%0],%1;" :: "l"(p), "r"(1u) : "memory");
}
__device__ __forceinline__ void barx(int id, int n) {
    asm volatile("bar.sync %0,%1;" :: "r"(id), "r"(n) : "memory");
}

// ---------------- init: seed hidden rows, zero all counters -------------------
__global__ void init_kernel(const float* __restrict__ h0) {
    int j = blockIdx.x * blockDim.x + threadIdx.x;
    if (j < DH2) {
        // torch layout h0[L*2, H]; layer0 dirs = rows 0,1 ; layer1 dirs = rows 2,3
        g_H0[j] = h0[j];
        g_H1[j] = h0[DH2 + j];
    }
    if (j < 4) ((unsigned*)g_cnt)[j] = 0u;
    if (j < 2 * NTILE_T) ((unsigned*)g_blk)[j] = 0u;
}

// ---------------- sequential chain (one layer, one direction per CTA) ---------
__device__ __forceinline__ void seq_pass(
    int layer, int d, int g,
    const float* __restrict__ Whh, const float* __restrict__ bhh,
    float* h_sh)
{
    const float* Gi = layer ? g_Gi1 : g_Gi0;
    float* Hs = layer ? g_H1 : g_H0;
    unsigned* cnt = &g_cnt[layer][d];
    const unsigned* blk = g_blk[layer];

    const int st   = threadIdx.x - HLP_THR;   // 0..383 within seq group
    const int sw   = st >> 5;                 // seq warp 0..11
    const int lane = threadIdx.x & 31;
    const int i = g * NWARP + sw;             // hidden index within direction
    const int u = d * HDIM + i;               // global unit index

    // Register-resident w_hh rows (r,z,n) as packed f32x2.
    unsigned long long wr[12], wz[12], wn[12];
    {
        const float* base = Whh + (size_t)d * G3 * HDIM;
        const unsigned long long* r64 = reinterpret_cast<const unsigned long long*>(base + (size_t)i * HDIM);
        const unsigned long long* z64 = reinterpret_cast<const unsigned long long*>(base + (size_t)(HDIM + i) * HDIM);
        const unsigned long long* n64 = reinterpret_cast<const unsigned long long*>(base + (size_t)(2 * HDIM + i) * HDIM);
#pragma unroll
        for (int m = 0; m < 12; m++) {
            int p = lane + 32 * m;
            wr[m] = r64[p]; wz[m] = z64[p]; wn[m] = n64[p];
        }
    }
    const float br = bhh[d * G3 + i];
    const float bz = bhh[d * G3 + HDIM + i];
    const float bn = bhh[d * G3 + 2 * HDIM + i];

    // Stage h row 0 (seeded by init kernel).
    {
        const float2* src = reinterpret_cast<const float2*>(Hs + d * HDIM);
        reinterpret_cast<float2*>(h_sh)[st] = __ldcg(src + st);
    }
    // Gate: first Gi block must be produced by helpers.
    if (sw == 0) {
        while (ldrelax(&blk[0]) < (unsigned)NTILE_M) { }
        fence_acqrel();
    }
    barx(1, SEQ_THR);

    float hprev = h_sh[i];

    for (int t = 0; t < T_STEPS; t++) {
        // Input-side gates for this step (block gated; row is L2-resident).
        float gr = 0.f, gz = 0.f, gn = 0.f;
        if (lane == 0) {
            const float* gp = Gi + (size_t)t * RTOT + d * G3 + i;
            gr = __ldg(gp); gz = __ldg(gp + HDIM); gn = __ldg(gp + 2 * HDIM);
        }

        // Packed h2h matvec from shared memory.
        const unsigned long long* h64 = reinterpret_cast<const unsigned long long*>(h_sh);
        unsigned long long ar = 0ull, az = 0ull, an = 0ull;
#pragma unroll
        for (int m = 0; m < 12; m++) {
            unsigned long long hv = h64[lane + 32 * m];
            ar = fma2(wr[m], hv, ar);
            az = fma2(wz[m], hv, az);
            an = fma2(wn[m], hv, an);
        }
        float2 fr = unpack2(ar), fz = unpack2(az), fn = unpack2(an);
        float sr = fr.x + fr.y, sz = fz.x + fz.y, sn = fn.x + fn.y;
#pragma unroll
        for (int off = 16; off > 0; off >>= 1) {
            sr += __shfl_down_sync(0xffffffffu, sr, off);
            sz += __shfl_down_sync(0xffffffffu, sz, off);
            sn += __shfl_down_sync(0xffffffffu, sn, off);
        }

        if (lane == 0) {
            float r = 1.f / (1.f + __expf(-(gr + sr + br)));
            float z = 1.f / (1.f + __expf(-(gz + sz + bz)));
            float n = tanhf(gn + r * (sn + bn));
            float hnew = (1.f - z) * n + z * hprev;
            hprev = hnew;
            __stcg(&Hs[(size_t)(t + 1) * DH2 + u], hnew);
        }
        barx(1, SEQ_THR);                       // all 12 seq warps' stores issued

        if (st == 0) {
            __threadfence();                     // publish this CTA's h stores
            red_add(cnt);                        // fire-and-forget arrival
        }
        if (sw == 0) {
            unsigned tgt = (unsigned)(t + 1) * GCTA;
            while (ldrelax(cnt) < tgt) { }
            if (((t + 1) & 63) == 0 && (t + 1) < T_STEPS) {
                const unsigned* bp = &blk[(t + 1) >> 6];
                while (ldrelax(bp) < (unsigned)NTILE_M) { }
            }
            fence_acqrel();
        }
        barx(1, SEQ_THR);

        // Stage h row t+1 (own direction: 3 KB).
        const float2* src = reinterpret_cast<const float2*>(Hs + (size_t)(t + 1) * DH2 + d * HDIM);
        reinterpret_cast<float2*>(h_sh)[st] = __ldcg(src + st);
        barx(1, SEQ_THR);
    }
}

// ---------------- helper GEMM group (4 warps, 128 threads) --------------------
// Computes 64t x 128m tiles of Gi0 then Gi1. Gi1 tiles gated on layer-0 progress.
__device__ __forceinline__ void helper_gemm(
    const float* __restrict__ x,
    const float* __restrict__ wih0, const float* __restrict__ bih0,
    const float* __restrict__ wih1, const float* __restrict__ bih1,
    float* sA, float* sB)
{
    const int gt = threadIdx.x;            // 0..127 within helper group
    const int tx = gt & 15, ty = gt >> 4;  // 16 m-threads x 8 t-threads
    const int hg = blockIdx.x;             // helper group id (one per CTA)

    for (int idx = hg; idx < 2 * TILES_PER; idx += NCTA) {
        const int which = (idx >= TILES_PER) ? 1 : 0;
        const int tau = which ? idx - TILES_PER : idx;
        const int trow = tau / NTILE_M, mcol = tau % NTILE_M;

        if (which) {
            // Gate: Gi1 tile needs h0 rows up to trow*64+64 -> layer0 steps done.
            if (gt == 0) {
                unsigned tgt = (unsigned)(trow + 1) * 64 * GCTA;
                while (ldrelax(&g_cnt[0][0]) < tgt || ldrelax(&g_cnt[0][1]) < tgt)
                    __nanosleep(256);
                fence_acqrel();
            }
            barx(2, HLP_THR);
        }

        const int K = which ? DH2 : D_INP;
        const float* Ab = which ? (g_H0 + (size_t)(trow * 64 + 1) * DH2)
                                : (x + (size_t)trow * 64 * D_INP);
        const float* Bb = (which ? wih1 : wih0) + (size_t)mcol * 128 * K;
        const float* bias = (which ? bih1 : bih0) + mcol * 128;
        float* Cb = (which ? g_Gi1 : g_Gi0) + (size_t)trow * 64 * RTOT + mcol * 128;

        unsigned long long acc2[8][4];
#pragma unroll
        for (int a = 0; a < 8; a++)
#pragma unroll
            for (int b = 0; b < 4; b++) acc2[a][b] = 0ull;

        for (int kb = 0; kb < K; kb += KB) {
            // Stage A (64 x 16): 256 float4 slots, 2 per thread.
#pragma unroll
            for (int q = 0; q < 2; q++) {
                int f = gt * 2 + q, r = f >> 2, c4 = (f & 3) * 4;
                float4 v = *reinterpret_cast<const float4*>(Ab + (size_t)r * K + kb + c4);
                sA[(c4 + 0) * 68 + r] = v.x; sA[(c4 + 1) * 68 + r] = v.y;
                sA[(c4 + 2) * 68 + r] = v.z; sA[(c4 + 3) * 68 + r] = v.w;
            }
            // Stage B (128 x 16): 512 float4 slots, 4 per thread.
#pragma unroll
            for (int q = 0; q < 4; q++) {
                int f = gt * 4 + q, r = f >> 2, c4 = (f & 3) * 4;
                float4 v = *reinterpret_cast<const float4*>(Bb + (size_t)r * K + kb + c4);
                sB[(c4 + 0) * 132 + r] = v.x; sB[(c4 + 1) * 132 + r] = v.y;
                sB[(c4 + 2) * 132 + r] = v.z; sB[(c4 + 3) * 132 + r] = v.w;
            }
            barx(2, HLP_THR);
#pragma unroll
            for (int k = 0; k < KB; k++) {
                float4 a0 = *reinterpret_cast<const float4*>(sA + k * 68 + ty * 8);
                float4 a1 = *reinterpret_cast<const float4*>(sA + k * 68 + ty * 8 + 4);
                float4 b0 = *reinterpret_cast<const float4*>(sB + k * 132 + tx * 8);
                float4 b1 = *reinterpret_cast<const float4*>(sB + k * 132 + tx * 8 + 4);
                unsigned long long rb2[4] = {pack2(b0.x, b0.y), pack2(b0.z, b0.w),
                                             pack2(b1.x, b1.y), pack2(b1.z, b1.w)};
                float ra[8] = {a0.x, a0.y, a0.z, a0.w, a1.x, a1.y, a1.z, a1.w};
#pragma unroll
                for (int a = 0; a < 8; a++) {
                    unsigned long long ra2 = pack2(ra[a], ra[a]);
#pragma unroll
                    for (int b = 0; b < 4; b++)
                        acc2[a][b] = fma2(ra2, rb2[b], acc2[a][b]);
                }
            }
            barx(2, HLP_THR);
        }

        // Store C tile (+bias).
#pragma unroll
        for (int a = 0; a < 8; a++) {
            float* Cp = Cb + (size_t)(ty * 8 + a) * RTOT + tx * 8;
            float2 f0 = unpack2(acc2[a][0]), f1 = unpack2(acc2[a][1]);
            float2 f2 = unpack2(acc2[a][2]), f3 = unpack2(acc2[a][3]);
            float4 v0 = make_float4(f0.x + bias[tx * 8 + 0], f0.y + bias[tx * 8 + 1],
                                    f1.x + bias[tx * 8 + 2], f1.y + bias[tx * 8 + 3]);
            float4 v1 = make_float4(f2.x + bias[tx * 8 + 4], f2.y + bias[tx * 8 + 5],
                                    f3.x + bias[tx * 8 + 6], f3.y + bias[tx * 8 + 7]);
            *reinterpret_cast<float4*>(Cp) = v0;
            *reinterpret_cast<float4*>(Cp + 4) = v1;
        }
        barx(2, HLP_THR);
        if (gt == 0) {
            __threadfence();
            red_add(&g_blk[which][trow]);
        }
    }
}

// ---------------- fused persistent kernel -------------------------------------
__global__ __launch_bounds__(NTHR) void fused_kernel(
    const float* __restrict__ x,
    const float* __restrict__ w_hh0, const float* __restrict__ b_hh0,
    const float* __restrict__ w_hh1, const float* __restrict__ b_hh1,
    const float* __restrict__ w_ih0, const float* __restrict__ b_ih0,
    const float* __restrict__ w_ih1, const float* __restrict__ b_ih1)
{
    __shared__ float sA[KB * 68];     // helper A tile (64 x 16, transposed, padded)
    __shared__ float sB[KB * 132];    // helper B tile (128 x 16, transposed, padded)
    __shared__ float h_sh[HDIM];      // seq hidden vector (own direction)

    const int d = blockIdx.x & 1;     // direction
    const int g = blockIdx.x >> 1;    // group-local CTA id (0..63)

    if (threadIdx.x < HLP_THR) {
        // Helper warps (wid 0..3, LOW priority under hi-wid-first arbiter).
        helper_gemm(x, w_ih0, b_ih0, w_ih1, b_ih1, sA, sB);
    } else {
        // Sequential warps (wid 4..15): layer 0 then layer 1.
        seq_pass(0, d, g, w_hh0, b_hh0, h_sh);
        seq_pass(1, d, g, w_hh1, b_hh1, h_sh);
    }
}

// ---------------- final FC + sigmoid ------------------------------------------
__global__ void fc_kernel(const float* __restrict__ fcw,
                          const float* __restrict__ fcb,
                          float* __restrict__ out)
{
    int gw = (blockIdx.x * blockDim.x + threadIdx.x) >> 5;   // output index
    int lane = threadIdx.x & 31;
    if (gw >= 256) return;
    const float* h = g_H1 + (size_t)T_STEPS * DH2;
    float acc = 0.f;
    for (int k = lane; k < DH2; k += 32)
        acc += fcw[(size_t)gw * DH2 + k] * h[k];
#pragma unroll
    for (int off = 16; off > 0; off >>= 1)
        acc += __shfl_down_sync(0xffffffffu, acc, off);
    if (lane == 0)
        out[gw] = 1.f / (1.f + __expf(-(acc + fcb[gw])));
}

// ---------------- launch ------------------------------------------------------
extern "C" void kernel_launch(void* const* d_in, const int* in_sizes, int n_in,
                              void* d_out, int out_size)
{
    const float* x     = (const float*)d_in[0];
    const float* h0    = (const float*)d_in[1];
    const float* w_ih0 = (const float*)d_in[2];
    const float* w_hh0 = (const float*)d_in[3];
    const float* b_ih0 = (const float*)d_in[4];
    const float* b_hh0 = (const float*)d_in[5];
    const float* w_ih1 = (const float*)d_in[6];
    const float* w_hh1 = (const float*)d_in[7];
    const float* b_ih1 = (const float*)d_in[8];
    const float* b_hh1 = (const float*)d_in[9];
    const float* fc_w  = (const float*)d_in[10];
    const float* fc_b  = (const float*)d_in[11];
    float* out = (float*)d_out;

    (void)in_sizes; (void)n_in; (void)out_size;

    init_kernel<<<6, 256>>>(h0);

    // One persistent kernel: GEMMs (helper warps) + both sequential passes.
    fused_kernel<<<NCTA, NTHR>>>(x, w_hh0, b_hh0, w_hh1, b_hh1,
                                 w_ih0, b_ih0, w_ih1, b_ih1);

    // final FC + sigmoid
    fc_kernel<<<32, 256>>>(fc_w, fc_b, out);
}

// round 15
// speedup vs baseline: 1.2870x; 1.2870x over previous
#include <cuda_runtime.h>
#include <cstdint>

// Problem constants
#define T_STEPS 8192
#define D_INP   512
#define HDIM    768      // H
#define G3      2304     // 3*H
#define RTOT    4608     // 2 dirs * 3H
#define DH2     1536     // 2*H
#define NCTA    128      // seq CTAs (64 per direction)
#define GCTA    64       // CTAs per direction group
#define NWARP   12       // GRU units per CTA; 64*12 = 768 = H per direction
#define NTHR    384
#define NT1_M   36       // Gi1 col tiles (4608/128)
#define NT1_T   64       // Gi1 row tiles (8192/128)
#define NT1     (NT1_M * NT1_T)   // 2304 Gi1 tiles

// ---------------- scratch (device globals; no allocation allowed) -------------
__device__ float g_Gi0[(size_t)T_STEPS * RTOT];
__device__ float g_Gi1[(size_t)T_STEPS * RTOT];
__device__ float g_H0[(size_t)(T_STEPS + 1) * DH2];
__device__ float g_H1[(size_t)(T_STEPS + 1) * DH2];
__device__ unsigned g_cnt[2][64];   // [layer][dir*32] padded to separate lines
__device__ unsigned g_q1;           // Gi1 tile queue head

// ---------------- helpers ------------------------------------------------------
__device__ __forceinline__ unsigned long long fma2(unsigned long long a,
                                                   unsigned long long b,
                                                   unsigned long long c) {
    unsigned long long d;
    asm("fma.rn.f32x2 %0,%1,%2,%3;" : "=l"(d) : "l"(a), "l"(b), "l"(c));
    return d;
}
__device__ __forceinline__ unsigned long long pack2(float x, float y) {
    unsigned long long r;
    asm("mov.b64 %0,{%1,%2};" : "=l"(r) : "f"(x), "f"(y));
    return r;
}
__device__ __forceinline__ float2 unpack2(unsigned long long v) {
    float2 f;
    asm("mov.b64 {%0,%1},%2;" : "=f"(f.x), "=f"(f.y) : "l"(v));
    return f;
}
__device__ __forceinline__ unsigned ldrelax(const unsigned* p) {
    unsigned v;
    asm volatile("ld.relaxed.gpu.global.u32 %0,[%1];" : "=r"(v) : "l"(p));
    return v;
}
__device__ __forceinline__ void fence_acqrel() {
    asm volatile("fence.acq_rel.gpu;" ::: "memory");
}
__device__ __forceinline__ void red_release(unsigned* p) {
    asm volatile("red.release.gpu.global.add.u32 [%0],%1;" :: "l"(p), "r"(1u) : "memory");
}
__device__ __forceinline__ void barx(int id, int n) {
    asm volatile("bar.sync %0,%1;" :: "r"(id), "r"(n) : "memory");
}

// ---------------- init ---------------------------------------------------------
__global__ void init_kernel(const float* __restrict__ h0) {
    int j = blockIdx.x * blockDim.x + threadIdx.x;
    if (j < DH2) {
        g_H0[j] = h0[j];          // layer0 dirs = rows 0,1
        g_H1[j] = h0[DH2 + j];    // layer1 dirs = rows 2,3
    }
    if (j < 128) ((unsigned*)g_cnt)[j] = 0u;
    if (j == 128) g_q1 = 0u;
}

// ---------------- 128x128 GEMM tile (NT), double-buffered, 256 threads --------
// C[r][c] = sum_k Ab[r][k] * Bb[c][k] + bias[c];  C row stride RTOT. bar id 3.
__device__ __forceinline__ void gemm_tile(
    const float* __restrict__ Ab, const float* __restrict__ Bb,
    const float* __restrict__ bias, float* __restrict__ Cb,
    int K, float* As, float* Bs)
{
    const int tid = threadIdx.x;        // 0..255
    const int tx = tid & 15, ty = tid >> 4;
    const int r0 = (tid * 2) >> 2,     c0 = ((tid * 2) & 3) * 4;
    const int r1 = (tid * 2 + 1) >> 2, c1 = ((tid * 2 + 1) & 3) * 4;

    unsigned long long acc2[8][4];
#pragma unroll
    for (int a = 0; a < 8; a++)
#pragma unroll
        for (int b = 0; b < 4; b++) acc2[a][b] = 0ull;

    float4 va0 = *reinterpret_cast<const float4*>(Ab + (size_t)r0 * K + c0);
    float4 va1 = *reinterpret_cast<const float4*>(Ab + (size_t)r1 * K + c1);
    float4 vb0 = *reinterpret_cast<const float4*>(Bb + (size_t)r0 * K + c0);
    float4 vb1 = *reinterpret_cast<const float4*>(Bb + (size_t)r1 * K + c1);
    As[(c0 + 0) * 128 + r0] = va0.x; As[(c0 + 1) * 128 + r0] = va0.y;
    As[(c0 + 2) * 128 + r0] = va0.z; As[(c0 + 3) * 128 + r0] = va0.w;
    As[(c1 + 0) * 128 + r1] = va1.x; As[(c1 + 1) * 128 + r1] = va1.y;
    As[(c1 + 2) * 128 + r1] = va1.z; As[(c1 + 3) * 128 + r1] = va1.w;
    Bs[(c0 + 0) * 128 + r0] = vb0.x; Bs[(c0 + 1) * 128 + r0] = vb0.y;
    Bs[(c0 + 2) * 128 + r0] = vb0.z; Bs[(c0 + 3) * 128 + r0] = vb0.w;
    Bs[(c1 + 0) * 128 + r1] = vb1.x; Bs[(c1 + 1) * 128 + r1] = vb1.y;
    Bs[(c1 + 2) * 128 + r1] = vb1.z; Bs[(c1 + 3) * 128 + r1] = vb1.w;
    barx(3, 256);

    int buf = 0;
    for (int k0 = 0; k0 < K; k0 += 16) {
        const bool more = (k0 + 16 < K);
        if (more) {
            va0 = *reinterpret_cast<const float4*>(Ab + (size_t)r0 * K + k0 + 16 + c0);
            va1 = *reinterpret_cast<const float4*>(Ab + (size_t)r1 * K + k0 + 16 + c1);
            vb0 = *reinterpret_cast<const float4*>(Bb + (size_t)r0 * K + k0 + 16 + c0);
            vb1 = *reinterpret_cast<const float4*>(Bb + (size_t)r1 * K + k0 + 16 + c1);
        }
        const float* Ap = As + buf * 2048;
        const float* Bp = Bs + buf * 2048;
#pragma unroll
        for (int kk = 0; kk < 16; kk++) {
            float4 a0 = *reinterpret_cast<const float4*>(Ap + kk * 128 + ty * 8);
            float4 a1 = *reinterpret_cast<const float4*>(Ap + kk * 128 + ty * 8 + 4);
            float4 b0 = *reinterpret_cast<const float4*>(Bp + kk * 128 + tx * 8);
            float4 b1 = *reinterpret_cast<const float4*>(Bp + kk * 128 + tx * 8 + 4);
            unsigned long long rb2[4] = {pack2(b0.x, b0.y), pack2(b0.z, b0.w),
                                         pack2(b1.x, b1.y), pack2(b1.z, b1.w)};
            float ra[8] = {a0.x, a0.y, a0.z, a0.w, a1.x, a1.y, a1.z, a1.w};
#pragma unroll
            for (int a = 0; a < 8; a++) {
                unsigned long long ra2 = pack2(ra[a], ra[a]);
#pragma unroll
                for (int b = 0; b < 4; b++)
                    acc2[a][b] = fma2(ra2, rb2[b], acc2[a][b]);
            }
        }
        if (more) {
            float* An = As + (buf ^ 1) * 2048;
            float* Bn = Bs + (buf ^ 1) * 2048;
            An[(c0 + 0) * 128 + r0] = va0.x; An[(c0 + 1) * 128 + r0] = va0.y;
            An[(c0 + 2) * 128 + r0] = va0.z; An[(c0 + 3) * 128 + r0] = va0.w;
            An[(c1 + 0) * 128 + r1] = va1.x; An[(c1 + 1) * 128 + r1] = va1.y;
            An[(c1 + 2) * 128 + r1] = va1.z; An[(c1 + 3) * 128 + r1] = va1.w;
            Bn[(c0 + 0) * 128 + r0] = vb0.x; Bn[(c0 + 1) * 128 + r0] = vb0.y;
            Bn[(c0 + 2) * 128 + r0] = vb0.z; Bn[(c0 + 3) * 128 + r0] = vb0.w;
            Bn[(c1 + 0) * 128 + r1] = vb1.x; Bn[(c1 + 1) * 128 + r1] = vb1.y;
            Bn[(c1 + 2) * 128 + r1] = vb1.z; Bn[(c1 + 3) * 128 + r1] = vb1.w;
            barx(3, 256);
        }
        buf ^= 1;
    }
#pragma unroll
    for (int a = 0; a < 8; a++) {
        float* Cp = Cb + (size_t)(ty * 8 + a) * RTOT + tx * 8;
        float2 f0 = unpack2(acc2[a][0]), f1 = unpack2(acc2[a][1]);
        float2 f2 = unpack2(acc2[a][2]), f3 = unpack2(acc2[a][3]);
        *reinterpret_cast<float4*>(Cp) =
            make_float4(f0.x + bias[tx * 8 + 0], f0.y + bias[tx * 8 + 1],
                        f1.x + bias[tx * 8 + 2], f1.y + bias[tx * 8 + 3]);
        *reinterpret_cast<float4*>(Cp + 4) =
            make_float4(f2.x + bias[tx * 8 + 4], f2.y + bias[tx * 8 + 5],
                        f3.x + bias[tx * 8 + 6], f3.y + bias[tx * 8 + 7]);
    }
}

// ---------------- Gi0 GEMM (standalone, grid 36 x 64, 256 threads) ------------
__global__ __launch_bounds__(256) void gemm0_kernel(
    const float* __restrict__ x, const float* __restrict__ wih0,
    const float* __restrict__ bih0)
{
    __shared__ float smem[8192];
    gemm_tile(x + (size_t)blockIdx.y * 128 * D_INP,
              wih0 + (size_t)blockIdx.x * 128 * D_INP,
              bih0 + blockIdx.x * 128,
              g_Gi0 + (size_t)blockIdx.y * 128 * RTOT + blockIdx.x * 128,
              D_INP, smem, smem + 4096);
}

// ---------------- sequential GRU pass (device side) ----------------------------
__device__ __forceinline__ void seq_pass(
    int layer, const float* __restrict__ Whh, const float* __restrict__ bhh,
    float* h_sh)
{
    const float* Gi = layer ? g_Gi1 : g_Gi0;
    float* Hs = layer ? g_H1 : g_H0;
    const int d = blockIdx.x & 1;
    const int g = blockIdx.x >> 1;
    unsigned* cnt = &g_cnt[layer][d * 32];

    const int warp = threadIdx.x >> 5;
    const int lane = threadIdx.x & 31;
    const int i = g * NWARP + warp;
    const int u = d * HDIM + i;

    unsigned long long wr[12], wz[12], wn[12];
    {
        const float* base = Whh + (size_t)d * G3 * HDIM;
        const unsigned long long* r64 = reinterpret_cast<const unsigned long long*>(base + (size_t)i * HDIM);
        const unsigned long long* z64 = reinterpret_cast<const unsigned long long*>(base + (size_t)(HDIM + i) * HDIM);
        const unsigned long long* n64 = reinterpret_cast<const unsigned long long*>(base + (size_t)(2 * HDIM + i) * HDIM);
#pragma unroll
        for (int m = 0; m < 12; m++) {
            int p = lane + 32 * m;
            wr[m] = r64[p]; wz[m] = z64[p]; wn[m] = n64[p];
        }
    }
    const float br = bhh[d * G3 + i];
    const float bz = bhh[d * G3 + HDIM + i];
    const float bn = bhh[d * G3 + 2 * HDIM + i];

    {   // stage h row 0
        const float2* src = reinterpret_cast<const float2*>(Hs + d * HDIM);
        reinterpret_cast<float2*>(h_sh)[threadIdx.x] = __ldcg(src + threadIdx.x);
    }
    __syncthreads();
    float hprev = h_sh[i];

    float gr = 0.f, gz = 0.f, gn = 0.f;
    if (lane == 0) {
        const float* gp = Gi + d * G3 + i;
        gr = __ldg(gp); gz = __ldg(gp + HDIM); gn = __ldg(gp + 2 * HDIM);
    }

    for (int t = 0; t < T_STEPS; t++) {
        const unsigned long long* h64 = reinterpret_cast<const unsigned long long*>(h_sh);
        unsigned long long ar = 0ull, az = 0ull, an = 0ull;
#pragma unroll
        for (int m = 0; m < 12; m++) {
            unsigned long long hv = h64[lane + 32 * m];
            ar = fma2(wr[m], hv, ar);
            az = fma2(wz[m], hv, az);
            an = fma2(wn[m], hv, an);
        }
        float2 fr = unpack2(ar), fz = unpack2(az), fn = unpack2(an);
        float sr = fr.x + fr.y, sz = fz.x + fz.y, sn = fn.x + fn.y;
#pragma unroll
        for (int off = 16; off > 0; off >>= 1) {
            sr += __shfl_down_sync(0xffffffffu, sr, off);
            sz += __shfl_down_sync(0xffffffffu, sz, off);
            sn += __shfl_down_sync(0xffffffffu, sn, off);
        }

        float gr_n = 0.f, gz_n = 0.f, gn_n = 0.f;
        if (lane == 0 && t + 1 < T_STEPS) {
            const float* gp = Gi + (size_t)(t + 1) * RTOT + d * G3 + i;
            gr_n = __ldg(gp); gz_n = __ldg(gp + HDIM); gn_n = __ldg(gp + 2 * HDIM);
        }

        if (lane == 0) {
            float r = 1.f / (1.f + __expf(-(gr + sr + br)));
            float z = 1.f / (1.f + __expf(-(gz + sz + bz)));
            float n = tanhf(gn + r * (sn + bn));
            float hnew = (1.f - z) * n + z * hprev;
            hprev = hnew;
            __stcg(&Hs[(size_t)(t + 1) * DH2 + u], hnew);
        }
        gr = gr_n; gz = gz_n; gn = gn_n;

        __syncthreads();                      // all 12 warps' stores issued
        if (warp == 0) {
            if (lane == 0) red_release(cnt);  // ordered arrival (no membar)
            unsigned tgt = (unsigned)(t + 1) * GCTA;
            while (ldrelax(cnt) < tgt) { }
            fence_acqrel();
            // warp 0 stages the whole 3 KB row itself (6 x float4 per lane)
            const float4* src = reinterpret_cast<const float4*>(
                Hs + (size_t)(t + 1) * DH2 + d * HDIM);
            float4 v[6];
#pragma unroll
            for (int q = 0; q < 6; q++) v[q] = __ldcg(src + q * 32 + lane);
#pragma unroll
            for (int q = 0; q < 6; q++)
                reinterpret_cast<float4*>(h_sh)[q * 32 + lane] = v[q];
        }
        __syncthreads();                      // release: h_sh ready
    }
}

// ---------------- pass kernel: seq CTAs + (layer0 only) Gi1 workers -----------
__global__ __launch_bounds__(NTHR) void pass_kernel(
    int layer,
    const float* __restrict__ Whh, const float* __restrict__ bhh,
    const float* __restrict__ wih1, const float* __restrict__ bih1)
{
    __shared__ float smem[8192];      // 32KB: gemm buffers / seq h_sh
    __shared__ unsigned s_n;

    if (blockIdx.x < NCTA) {
        seq_pass(layer, Whh, bhh, smem);
        return;
    }
    if (layer != 0) return;
    if (threadIdx.x >= 256) return;   // workers use 256 threads

    const unsigned fin = (unsigned)T_STEPS * GCTA;
    for (;;) {
        if (threadIdx.x == 0) {
            unsigned n;
            if (ldrelax(&g_cnt[0][0]) >= fin && ldrelax(&g_cnt[0][32]) >= fin)
                n = 0xFFFFFFFFu;               // pass0 done: stop grabbing
            else
                n = atomicAdd(&g_q1, 1u);
            s_n = n;
        }
        barx(3, 256);
        unsigned n = s_n;
        if (n >= NT1) break;
        int trow = n / NT1_M, mcol = n % NT1_M;
        if (threadIdx.x == 0) {
            unsigned tgt = (unsigned)(trow + 1) * 128u * GCTA;
            while (ldrelax(&g_cnt[0][0]) < tgt || ldrelax(&g_cnt[0][32]) < tgt)
                __nanosleep(512);
            fence_acqrel();
        }
        barx(3, 256);
        gemm_tile(g_H0 + ((size_t)trow * 128 + 1) * DH2,
                  wih1 + (size_t)mcol * 128 * DH2,
                  bih1 + mcol * 128,
                  g_Gi1 + (size_t)trow * 128 * RTOT + mcol * 128,
                  DH2, smem, smem + 4096);
        barx(3, 256);
    }
}

// ---------------- Gi1 cleanup: tiles the in-pass workers didn't reach ---------
__global__ __launch_bounds__(256) void gi1_cleanup(
    const float* __restrict__ wih1, const float* __restrict__ bih1)
{
    __shared__ float smem[8192];
    unsigned head = *(volatile unsigned*)&g_q1;   // all tiles < head are done
    unsigned n = blockIdx.x;
    if (n < head) return;
    int trow = n / NT1_M, mcol = n % NT1_M;
    gemm_tile(g_H0 + ((size_t)trow * 128 + 1) * DH2,
              wih1 + (size_t)mcol * 128 * DH2,
              bih1 + mcol * 128,
              g_Gi1 + (size_t)trow * 128 * RTOT + mcol * 128,
              DH2, smem, smem + 4096);
}

// ---------------- final FC + sigmoid ------------------------------------------
__global__ void fc_kernel(const float* __restrict__ fcw,
                          const float* __restrict__ fcb,
                          float* __restrict__ out)
{
    int gw = (blockIdx.x * blockDim.x + threadIdx.x) >> 5;
    int lane = threadIdx.x & 31;
    if (gw >= 256) return;
    const float* h = g_H1 + (size_t)T_STEPS * DH2;
    float acc = 0.f;
    for (int k = lane; k < DH2; k += 32)
        acc += fcw[(size_t)gw * DH2 + k] * h[k];
#pragma unroll
    for (int off = 16; off > 0; off >>= 1)
        acc += __shfl_down_sync(0xffffffffu, acc, off);
    if (lane == 0)
        out[gw] = 1.f / (1.f + __expf(-(acc + fcb[gw])));
}

// ---------------- launch ------------------------------------------------------
extern "C" void kernel_launch(void* const* d_in, const int* in_sizes, int n_in,
                              void* d_out, int out_size)
{
    const float* x     = (const float*)d_in[0];
    const float* h0    = (const float*)d_in[1];
    const float* w_ih0 = (const float*)d_in[2];
    const float* w_hh0 = (const float*)d_in[3];
    const float* b_ih0 = (const float*)d_in[4];
    const float* b_hh0 = (const float*)d_in[5];
    const float* w_ih1 = (const float*)d_in[6];
    const float* w_hh1 = (const float*)d_in[7];
    const float* b_ih1 = (const float*)d_in[8];
    const float* b_hh1 = (const float*)d_in[9];
    const float* fc_w  = (const float*)d_in[10];
    const float* fc_b  = (const float*)d_in[11];
    float* out = (float*)d_out;

    (void)in_sizes; (void)n_in; (void)out_size;

    init_kernel<<<6, 256>>>(h0);

    // Gi0 = W_ih0 @ x + b_ih0
    gemm0_kernel<<<dim3(NT1_M, 64), 256>>>(x, w_ih0, b_ih0);

    // pass 0: 128 seq CTAs + 20 Gi1 GEMM workers on the spare SMs
    pass_kernel<<<NCTA + 20, NTHR>>>(0, w_hh0, b_hh0, w_ih1, b_ih1);

    // finish remaining Gi1 tiles at full width
    gi1_cleanup<<<NT1, 256>>>(w_ih1, b_ih1);

    // pass 1 (Gi1 fully materialized; no workers)
    pass_kernel<<<NCTA, NTHR>>>(1, w_hh1, b_hh1, w_ih1, b_ih1);

    // final FC + sigmoid
    fc_kernel<<<32, 256>>>(fc_w, fc_b, out);
}

// round 16
// speedup vs baseline: 1.8838x; 1.4637x over previous
#include <cuda_runtime.h>
#include <cstdint>

// Problem constants
#define T_STEPS 8192
#define D_INP   512
#define HDIM    768      // H
#define G3      2304     // 3*H
#define RTOT    4608     // 2 dirs * 3H
#define DH2     1536     // 2*H
#define GCTA    32       // CTAs per (layer,dir) group
#define NWARP   24       // GRU units per CTA (one warp each); 32*24 = 768
#define NTHR    768
#define NWORK   20       // Gi1 worker CTAs
#define NT1_M   36       // Gi1 col tiles (4608/128)
#define NT1_T   64       // Gi1 row tiles (8192/128)
#define NT1     (NT1_M * NT1_T)   // 2304 Gi1 tiles
#define SEQ_SMEM ((HDIM + NWARP * HDIM) * 4)   // h_sh + n-rows = 76800 B

// ---------------- scratch (device globals; no allocation allowed) -------------
__device__ float g_Gi0[(size_t)T_STEPS * RTOT];
__device__ float g_Gi1[(size_t)T_STEPS * RTOT];
__device__ float g_H0[(size_t)(T_STEPS + 1) * DH2];
__device__ float g_H1[(size_t)(T_STEPS + 1) * DH2];
__device__ unsigned g_cnt[2][64];   // [layer][dir*32] padded to separate lines
__device__ unsigned g_blk1[NT1_T];  // finished Gi1 tiles per t-row
__device__ unsigned g_q1;           // Gi1 tile queue head

// ---------------- helpers ------------------------------------------------------
__device__ __forceinline__ unsigned long long fma2(unsigned long long a,
                                                   unsigned long long b,
                                                   unsigned long long c) {
    unsigned long long d;
    asm("fma.rn.f32x2 %0,%1,%2,%3;" : "=l"(d) : "l"(a), "l"(b), "l"(c));
    return d;
}
__device__ __forceinline__ unsigned long long pack2(float x, float y) {
    unsigned long long r;
    asm("mov.b64 %0,{%1,%2};" : "=l"(r) : "f"(x), "f"(y));
    return r;
}
__device__ __forceinline__ float2 unpack2(unsigned long long v) {
    float2 f;
    asm("mov.b64 {%0,%1},%2;" : "=f"(f.x), "=f"(f.y) : "l"(v));
    return f;
}
__device__ __forceinline__ unsigned ldrelax(const unsigned* p) {
    unsigned v;
    asm volatile("ld.relaxed.gpu.global.u32 %0,[%1];" : "=r"(v) : "l"(p));
    return v;
}
__device__ __forceinline__ void fence_acqrel() {
    asm volatile("fence.acq_rel.gpu;" ::: "memory");
}
__device__ __forceinline__ void red_release(unsigned* p) {
    asm volatile("red.release.gpu.global.add.u32 [%0],%1;" :: "l"(p), "r"(1u) : "memory");
}
__device__ __forceinline__ void barx(int id, int n) {
    asm volatile("bar.sync %0,%1;" :: "r"(id), "r"(n) : "memory");
}

// ---------------- init ---------------------------------------------------------
__global__ void init_kernel(const float* __restrict__ h0) {
    int j = blockIdx.x * blockDim.x + threadIdx.x;
    if (j < DH2) {
        g_H0[j] = h0[j];          // layer0 dirs = rows 0,1
        g_H1[j] = h0[DH2 + j];    // layer1 dirs = rows 2,3
    }
    if (j < 128) ((unsigned*)g_cnt)[j] = 0u;
    else if (j < 128 + NT1_T) g_blk1[j - 128] = 0u;
    else if (j == 192) g_q1 = 0u;
}

// ---------------- 128x128 GEMM tile (256 threads, full regs) — for Gi0 --------
__device__ __forceinline__ void gemm_tile256(
    const float* __restrict__ Ab, const float* __restrict__ Bb,
    const float* __restrict__ bias, float* __restrict__ Cb,
    int K, float* As, float* Bs)
{
    const int tid = threadIdx.x;
    const int tx = tid & 15, ty = tid >> 4;
    const int r0 = (tid * 2) >> 2,     c0 = ((tid * 2) & 3) * 4;
    const int r1 = (tid * 2 + 1) >> 2, c1 = ((tid * 2 + 1) & 3) * 4;

    unsigned long long acc2[8][4];
#pragma unroll
    for (int a = 0; a < 8; a++)
#pragma unroll
        for (int b = 0; b < 4; b++) acc2[a][b] = 0ull;

    float4 va0 = *reinterpret_cast<const float4*>(Ab + (size_t)r0 * K + c0);
    float4 va1 = *reinterpret_cast<const float4*>(Ab + (size_t)r1 * K + c1);
    float4 vb0 = *reinterpret_cast<const float4*>(Bb + (size_t)r0 * K + c0);
    float4 vb1 = *reinterpret_cast<const float4*>(Bb + (size_t)r1 * K + c1);
    As[(c0 + 0) * 128 + r0] = va0.x; As[(c0 + 1) * 128 + r0] = va0.y;
    As[(c0 + 2) * 128 + r0] = va0.z; As[(c0 + 3) * 128 + r0] = va0.w;
    As[(c1 + 0) * 128 + r1] = va1.x; As[(c1 + 1) * 128 + r1] = va1.y;
    As[(c1 + 2) * 128 + r1] = va1.z; As[(c1 + 3) * 128 + r1] = va1.w;
    Bs[(c0 + 0) * 128 + r0] = vb0.x; Bs[(c0 + 1) * 128 + r0] = vb0.y;
    Bs[(c0 + 2) * 128 + r0] = vb0.z; Bs[(c0 + 3) * 128 + r0] = vb0.w;
    Bs[(c1 + 0) * 128 + r1] = vb1.x; Bs[(c1 + 1) * 128 + r1] = vb1.y;
    Bs[(c1 + 2) * 128 + r1] = vb1.z; Bs[(c1 + 3) * 128 + r1] = vb1.w;
    barx(3, 256);

    int buf = 0;
    for (int k0 = 0; k0 < K; k0 += 16) {
        const bool more = (k0 + 16 < K);
        if (more) {
            va0 = *reinterpret_cast<const float4*>(Ab + (size_t)r0 * K + k0 + 16 + c0);
            va1 = *reinterpret_cast<const float4*>(Ab + (size_t)r1 * K + k0 + 16 + c1);
            vb0 = *reinterpret_cast<const float4*>(Bb + (size_t)r0 * K + k0 + 16 + c0);
            vb1 = *reinterpret_cast<const float4*>(Bb + (size_t)r1 * K + k0 + 16 + c1);
        }
        const float* Ap = As + buf * 2048;
        const float* Bp = Bs + buf * 2048;
#pragma unroll
        for (int kk = 0; kk < 16; kk++) {
            float4 a0 = *reinterpret_cast<const float4*>(Ap + kk * 128 + ty * 8);
            float4 a1 = *reinterpret_cast<const float4*>(Ap + kk * 128 + ty * 8 + 4);
            float4 b0 = *reinterpret_cast<const float4*>(Bp + kk * 128 + tx * 8);
            float4 b1 = *reinterpret_cast<const float4*>(Bp + kk * 128 + tx * 8 + 4);
            unsigned long long rb2[4] = {pack2(b0.x, b0.y), pack2(b0.z, b0.w),
                                         pack2(b1.x, b1.y), pack2(b1.z, b1.w)};
            float ra[8] = {a0.x, a0.y, a0.z, a0.w, a1.x, a1.y, a1.z, a1.w};
#pragma unroll
            for (int a = 0; a < 8; a++) {
                unsigned long long ra2 = pack2(ra[a], ra[a]);
#pragma unroll
                for (int b = 0; b < 4; b++)
                    acc2[a][b] = fma2(ra2, rb2[b], acc2[a][b]);
            }
        }
        if (more) {
            float* An = As + (buf ^ 1) * 2048;
            float* Bn = Bs + (buf ^ 1) * 2048;
            An[(c0 + 0) * 128 + r0] = va0.x; An[(c0 + 1) * 128 + r0] = va0.y;
            An[(c0 + 2) * 128 + r0] = va0.z; An[(c0 + 3) * 128 + r0] = va0.w;
            An[(c1 + 0) * 128 + r1] = va1.x; An[(c1 + 1) * 128 + r1] = va1.y;
            An[(c1 + 2) * 128 + r1] = va1.z; An[(c1 + 3) * 128 + r1] = va1.w;
            Bn[(c0 + 0) * 128 + r0] = vb0.x; Bn[(c0 + 1) * 128 + r0] = vb0.y;
            Bn[(c0 + 2) * 128 + r0] = vb0.z; Bn[(c0 + 3) * 128 + r0] = vb0.w;
            Bn[(c1 + 0) * 128 + r1] = vb1.x; Bn[(c1 + 1) * 128 + r1] = vb1.y;
            Bn[(c1 + 2) * 128 + r1] = vb1.z; Bn[(c1 + 3) * 128 + r1] = vb1.w;
            barx(3, 256);
        }
        buf ^= 1;
    }
#pragma unroll
    for (int a = 0; a < 8; a++) {
        float* Cp = Cb + (size_t)(ty * 8 + a) * RTOT + tx * 8;
        float2 f0 = unpack2(acc2[a][0]), f1 = unpack2(acc2[a][1]);
        float2 f2 = unpack2(acc2[a][2]), f3 = unpack2(acc2[a][3]);
        *reinterpret_cast<float4*>(Cp) =
            make_float4(f0.x + bias[tx * 8 + 0], f0.y + bias[tx * 8 + 1],
                        f1.x + bias[tx * 8 + 2], f1.y + bias[tx * 8 + 3]);
        *reinterpret_cast<float4*>(Cp + 4) =
            make_float4(f2.x + bias[tx * 8 + 4], f2.y + bias[tx * 8 + 5],
                        f3.x + bias[tx * 8 + 6], f3.y + bias[tx * 8 + 7]);
    }
}

// ---------------- Gi0 GEMM (standalone, full chip, before the pass) -----------
__global__ __launch_bounds__(256) void gemm0_kernel(
    const float* __restrict__ x, const float* __restrict__ wih0,
    const float* __restrict__ bih0)
{
    __shared__ float smem[8192];
    gemm_tile256(x + (size_t)blockIdx.y * 128 * D_INP,
                 wih0 + (size_t)blockIdx.x * 128 * D_INP,
                 bih0 + blockIdx.x * 128,
                 g_Gi0 + (size_t)blockIdx.y * 128 * RTOT + blockIdx.x * 128,
                 D_INP, smem, smem + 4096);
}

// ---------------- sequential GRU chain: one (layer, dir) unit-warp CTA --------
// 24 warps = 24 GRU units. r,z weight rows in registers (packed f32x2);
// n row in dynamic shared memory (72 KB). Layer-1 additionally gates its Gi
// reads on worker-produced tile rows (checked only at 128-step boundaries).
__device__ __forceinline__ void seq_pass(
    int layer, int d, int g,
    const float* __restrict__ Whh, const float* __restrict__ bhh,
    float* smem)
{
    const float* Gi = layer ? g_Gi1 : g_Gi0;
    float* Hs = layer ? g_H1 : g_H0;
    unsigned* cnt = &g_cnt[layer][d * 32];

    float* h_sh = smem;               // HDIM floats
    float* nsh  = smem + HDIM;        // NWARP * HDIM floats

    const int warp = threadIdx.x >> 5;
    const int lane = threadIdx.x & 31;
    const int i = g * NWARP + warp;   // hidden index within direction
    const int u = d * HDIM + i;

    // r,z rows in registers; n row into shared.
    unsigned long long wr[12], wz[12];
    {
        const float* base = Whh + (size_t)d * G3 * HDIM;
        const unsigned long long* r64 = reinterpret_cast<const unsigned long long*>(base + (size_t)i * HDIM);
        const unsigned long long* z64 = reinterpret_cast<const unsigned long long*>(base + (size_t)(HDIM + i) * HDIM);
#pragma unroll
        for (int m = 0; m < 12; m++) {
            int p = lane + 32 * m;
            wr[m] = r64[p]; wz[m] = z64[p];
        }
        const float4* nsrc = reinterpret_cast<const float4*>(base + (size_t)(2 * HDIM + i) * HDIM);
        float4* ndst = reinterpret_cast<float4*>(nsh + warp * HDIM);
#pragma unroll
        for (int q = 0; q < 6; q++) ndst[q * 32 + lane] = nsrc[q * 32 + lane];
    }
    const float br = bhh[d * G3 + i];
    const float bz = bhh[d * G3 + HDIM + i];
    const float bn = bhh[d * G3 + 2 * HDIM + i];

    // stage h row 0 (768 floats, one per thread)
    h_sh[threadIdx.x] = __ldcg(Hs + d * HDIM + threadIdx.x);
    __syncthreads();
    float hprev = h_sh[i];

    // layer 1: first Gi1 tile row must exist before the step-0 prefetch.
    if (layer == 1) {
        if (threadIdx.x == 0) {
            while (ldrelax(&g_blk1[0]) < (unsigned)NT1_M) __nanosleep(256);
            fence_acqrel();
        }
        __syncthreads();
    }

    float gr = 0.f, gz = 0.f, gn = 0.f;
    if (lane == 0) {
        const float* gp = Gi + d * G3 + i;
        gr = __ldg(gp); gz = __ldg(gp + HDIM); gn = __ldg(gp + 2 * HDIM);
    }

    const unsigned long long* n64 =
        reinterpret_cast<const unsigned long long*>(nsh + warp * HDIM);

    for (int t = 0; t < T_STEPS; t++) {
        const unsigned long long* h64 = reinterpret_cast<const unsigned long long*>(h_sh);
        unsigned long long ar = 0ull, az = 0ull, an = 0ull;
#pragma unroll
        for (int m = 0; m < 12; m++) {
            unsigned long long hv = h64[lane + 32 * m];
            ar = fma2(wr[m], hv, ar);
            az = fma2(wz[m], hv, az);
            an = fma2(n64[lane + 32 * m], hv, an);
        }
        float2 fr = unpack2(ar), fz = unpack2(az), fn = unpack2(an);
        float sr = fr.x + fr.y, sz = fz.x + fz.y, sn = fn.x + fn.y;
#pragma unroll
        for (int off = 16; off > 0; off >>= 1) {
            sr += __shfl_down_sync(0xffffffffu, sr, off);
            sz += __shfl_down_sync(0xffffffffu, sz, off);
            sn += __shfl_down_sync(0xffffffffu, sn, off);
        }

        // prefetch next step's Gi (availability of its tile row was gated at
        // the END of the previous step's barrier).
        float gr_n = 0.f, gz_n = 0.f, gn_n = 0.f;
        if (lane == 0 && t + 1 < T_STEPS) {
            const float* gp = Gi + (size_t)(t + 1) * RTOT + d * G3 + i;
            gr_n = __ldg(gp); gz_n = __ldg(gp + HDIM); gn_n = __ldg(gp + 2 * HDIM);
        }

        if (lane == 0) {
            float r = 1.f / (1.f + __expf(-(gr + sr + br)));
            float z = 1.f / (1.f + __expf(-(gz + sz + bz)));
            float n = tanhf(gn + r * (sn + bn));
            float hnew = (1.f - z) * n + z * hprev;
            hprev = hnew;
            __stcg(&Hs[(size_t)(t + 1) * DH2 + u], hnew);
        }
        gr = gr_n; gz = gz_n; gn = gn_n;

        __syncthreads();                      // all 24 warps' stores issued
        if (warp == 0) {
            if (lane == 0) red_release(cnt);  // ordered arrival
            unsigned tgt = (unsigned)(t + 1) * GCTA;
            while (ldrelax(cnt) < tgt) { }
            // layer 1: gate the tile row needed by NEXT step's prefetch.
            if (layer == 1 && lane == 0 && ((t + 2) & 127) == 0 && t + 2 < T_STEPS) {
                const unsigned* bp = &g_blk1[(t + 2) >> 7];
                while (ldrelax(bp) < (unsigned)NT1_M) __nanosleep(128);
            }
            __syncwarp();
            fence_acqrel();
            // warp 0 stages h row t+1 (768 floats = 6 float4 per lane)
            const float4* src = reinterpret_cast<const float4*>(
                Hs + (size_t)(t + 1) * DH2 + d * HDIM);
            float4 v[6];
#pragma unroll
            for (int q = 0; q < 6; q++) v[q] = __ldcg(src + q * 32 + lane);
#pragma unroll
            for (int q = 0; q < 6; q++)
                reinterpret_cast<float4*>(h_sh)[q * 32 + lane] = v[q];
        }
        __syncthreads();                      // h_sh ready
    }
}

// ---------------- Gi1 worker (512 active threads, <=85 regs) -------------------
// 128t x 128m tiles, 8x4 (f32x2-packed) microtile, double-buffered staging.
__device__ __forceinline__ void worker_gi1(
    const float* __restrict__ wih1, const float* __restrict__ bih1,
    float* smem, unsigned* s_n)
{
    const int tid = threadIdx.x;          // 0..511
    const int tx = tid & 31, ty = tid >> 5;       // 32 m-thr x 16 t-thr
    const int r = tid >> 2, c4 = (tid & 3) * 4;   // staging slot (1 float4)
    float* As = smem;                     // 2 x 2048 floats
    float* Bs = smem + 4096;              // 2 x 2048 floats

    for (;;) {
        if (tid == 0) *s_n = atomicAdd(&g_q1, 1u);
        barx(3, 512);
        unsigned n = *s_n;
        barx(3, 512);
        if (n >= NT1) break;
        const int trow = n / NT1_M, mcol = n % NT1_M;

        // Gate on layer-0 progress (h0 rows trow*128+1 .. +128 must exist).
        if (tid == 0) {
            unsigned tgt = (unsigned)(trow + 1) * 128u * GCTA;
            while (ldrelax(&g_cnt[0][0]) < tgt || ldrelax(&g_cnt[0][32]) < tgt)
                __nanosleep(512);
            fence_acqrel();
        }
        barx(3, 512);

        const float* Ab = g_H0 + ((size_t)trow * 128 + 1) * DH2;
        const float* Bb = wih1 + (size_t)mcol * 128 * DH2;
        const float* bias = bih1 + mcol * 128 + tx * 4;
        float* Cb = g_Gi1 + (size_t)trow * 128 * RTOT + mcol * 128;

        unsigned long long acc2[8][2];
#pragma unroll
        for (int a = 0; a < 8; a++) { acc2[a][0] = 0ull; acc2[a][1] = 0ull; }

        float4 va = *reinterpret_cast<const float4*>(Ab + (size_t)r * DH2 + c4);
        float4 vb = *reinterpret_cast<const float4*>(Bb + (size_t)r * DH2 + c4);
        As[(c4 + 0) * 128 + r] = va.x; As[(c4 + 1) * 128 + r] = va.y;
        As[(c4 + 2) * 128 + r] = va.z; As[(c4 + 3) * 128 + r] = va.w;
        Bs[(c4 + 0) * 128 + r] = vb.x; Bs[(c4 + 1) * 128 + r] = vb.y;
        Bs[(c4 + 2) * 128 + r] = vb.z; Bs[(c4 + 3) * 128 + r] = vb.w;
        barx(3, 512);

        int buf = 0;
        for (int k0 = 0; k0 < DH2; k0 += 16) {
            const bool more = (k0 + 16 < DH2);
            if (more) {
                va = *reinterpret_cast<const float4*>(Ab + (size_t)r * DH2 + k0 + 16 + c4);
                vb = *reinterpret_cast<const float4*>(Bb + (size_t)r * DH2 + k0 + 16 + c4);
            }
            const float* Ap = As + buf * 2048;
            const float* Bp = Bs + buf * 2048;
#pragma unroll
            for (int kk = 0; kk < 16; kk++) {
                float4 a0 = *reinterpret_cast<const float4*>(Ap + kk * 128 + ty * 8);
                float4 a1 = *reinterpret_cast<const float4*>(Ap + kk * 128 + ty * 8 + 4);
                float4 b  = *reinterpret_cast<const float4*>(Bp + kk * 128 + tx * 4);
                unsigned long long rb0 = pack2(b.x, b.y), rb1 = pack2(b.z, b.w);
                float ra[8] = {a0.x, a0.y, a0.z, a0.w, a1.x, a1.y, a1.z, a1.w};
#pragma unroll
                for (int a = 0; a < 8; a++) {
                    unsigned long long ra2 = pack2(ra[a], ra[a]);
                    acc2[a][0] = fma2(ra2, rb0, acc2[a][0]);
                    acc2[a][1] = fma2(ra2, rb1, acc2[a][1]);
                }
            }
            if (more) {
                float* An = As + (buf ^ 1) * 2048;
                float* Bn = Bs + (buf ^ 1) * 2048;
                An[(c4 + 0) * 128 + r] = va.x; An[(c4 + 1) * 128 + r] = va.y;
                An[(c4 + 2) * 128 + r] = va.z; An[(c4 + 3) * 128 + r] = va.w;
                Bn[(c4 + 0) * 128 + r] = vb.x; Bn[(c4 + 1) * 128 + r] = vb.y;
                Bn[(c4 + 2) * 128 + r] = vb.z; Bn[(c4 + 3) * 128 + r] = vb.w;
                barx(3, 512);
            }
            buf ^= 1;
        }

        float4 bv = *reinterpret_cast<const float4*>(bias);
#pragma unroll
        for (int a = 0; a < 8; a++) {
            float2 f0 = unpack2(acc2[a][0]), f1 = unpack2(acc2[a][1]);
            *reinterpret_cast<float4*>(Cb + (size_t)(ty * 8 + a) * RTOT + tx * 4) =
                make_float4(f0.x + bv.x, f0.y + bv.y, f1.x + bv.z, f1.y + bv.w);
        }
        barx(3, 512);
        if (tid == 0) red_release(&g_blk1[trow]);
        barx(3, 512);
    }
}

// ---------------- fused pass: both layers + Gi1 workers, one kernel -----------
__global__ __launch_bounds__(NTHR, 1) void pass_kernel(
    const float* __restrict__ w_hh0, const float* __restrict__ b_hh0,
    const float* __restrict__ w_hh1, const float* __restrict__ b_hh1,
    const float* __restrict__ w_ih1, const float* __restrict__ b_ih1)
{
    extern __shared__ float smem[];
    __shared__ unsigned s_n;
    const int bid = blockIdx.x;

    if (bid < 128) {
        const int layer = bid >> 6;        // 0..63 -> layer0, 64..127 -> layer1
        const int lb = bid & 63;
        seq_pass(layer, lb & 1, lb >> 1,
                 layer ? w_hh1 : w_hh0, layer ? b_hh1 : b_hh0, smem);
    } else {
        if (threadIdx.x >= 512) return;    // workers use 512 threads
        worker_gi1(w_ih1, b_ih1, smem, &s_n);
    }
}

// ---------------- final FC + sigmoid ------------------------------------------
__global__ void fc_kernel(const float* __restrict__ fcw,
                          const float* __restrict__ fcb,
                          float* __restrict__ out)
{
    int gw = (blockIdx.x * blockDim.x + threadIdx.x) >> 5;
    int lane = threadIdx.x & 31;
    if (gw >= 256) return;
    const float* h = g_H1 + (size_t)T_STEPS * DH2;
    float acc = 0.f;
    for (int k = lane; k < DH2; k += 32)
        acc += fcw[(size_t)gw * DH2 + k] * h[k];
#pragma unroll
    for (int off = 16; off > 0; off >>= 1)
        acc += __shfl_down_sync(0xffffffffu, acc, off);
    if (lane == 0)
        out[gw] = 1.f / (1.f + __expf(-(acc + fcb[gw])));
}

// ---------------- launch ------------------------------------------------------
extern "C" void kernel_launch(void* const* d_in, const int* in_sizes, int n_in,
                              void* d_out, int out_size)
{
    const float* x     = (const float*)d_in[0];
    const float* h0    = (const float*)d_in[1];
    const float* w_ih0 = (const float*)d_in[2];
    const float* w_hh0 = (const float*)d_in[3];
    const float* b_ih0 = (const float*)d_in[4];
    const float* b_hh0 = (const float*)d_in[5];
    const float* w_ih1 = (const float*)d_in[6];
    const float* w_hh1 = (const float*)d_in[7];
    const float* b_ih1 = (const float*)d_in[8];
    const float* b_hh1 = (const float*)d_in[9];
    const float* fc_w  = (const float*)d_in[10];
    const float* fc_b  = (const float*)d_in[11];
    float* out = (float*)d_out;

    (void)in_sizes; (void)n_in; (void)out_size;

    // 76.8 KB dynamic smem needs an opt-in (idempotent; not a stream op).
    cudaFuncSetAttribute(pass_kernel,
                         cudaFuncAttributeMaxDynamicSharedMemorySize, SEQ_SMEM);

    init_kernel<<<6, 256>>>(h0);

    // Gi0 fully materialized up front (layer 0 consumes it immediately).
    gemm0_kernel<<<dim3(NT1_M, 64), 256>>>(x, w_ih0, b_ih0);

    // Both GRU layers run CONCURRENTLY (layer 1 trails by ~128 steps),
    // with 20 worker CTAs producing Gi1 just-in-time on spare SMs.
    pass_kernel<<<128 + NWORK, NTHR, SEQ_SMEM>>>(
        w_hh0, b_hh0, w_hh1, b_hh1, w_ih1, b_ih1);

    fc_kernel<<<32, 256>>>(fc_w, fc_b, out);
}